// round 1
// baseline (speedup 1.0000x reference)
#include <cuda_runtime.h>
#include <cstdint>

// Problem constants
#define B_     16
#define N_     256
#define DIM_   768
#define HEADS_ 12
#define DHEAD_ 64
#define BH_    (B_*HEADS_)      // 192
#define MAREA  2025
#define ROWS_  (B_*N_)          // 4096

// ---------------- scratch (static device globals; no allocations) ----------
__device__ float g_weff   [DIM_ * 3 * DIM_];           // [768][2304] composed weights
__device__ float g_biasqkv[3 * DIM_];                  // concat b_q|b_k|b_v
__device__ float g_qkvh   [(size_t)ROWS_ * 3 * DIM_];  // [4096][2304] qh|kh|vh
__device__ float g_karea  [(size_t)BH_ * MAREA * DHEAD_]; // [192][2025][64] means
__device__ float g_varea  [(size_t)BH_ * MAREA * DHEAD_]; // sums
__device__ float g_attn   [(size_t)ROWS_ * DIM_];      // [4096][768]

// ---------------- bias concat -------------------------------------------
__global__ void bias_concat_kernel(const float* __restrict__ bq,
                                   const float* __restrict__ bk,
                                   const float* __restrict__ bv) {
    int c = blockIdx.x * 768 + threadIdx.x;
    const float* src = (blockIdx.x == 0) ? bq : (blockIdx.x == 1) ? bk : bv;
    g_biasqkv[c] = src[threadIdx.x];
}

// ---------------- generic tiled SGEMM: C = A[MxK] @ B[KxN] (+bias) --------
// BM=BN=64, BK=16, 256 threads, 4x4 microtile. All dims divisible by 64/16.
__global__ __launch_bounds__(256)
void gemm64_kernel(const float* __restrict__ A, int lda,
                   const float* __restrict__ Bm, int ldb,
                   float* __restrict__ C, int ldc,
                   int K, const float* __restrict__ bias) {
    __shared__ float As[16][64];
    __shared__ float Bs[16][64];
    int t  = threadIdx.x;
    int tx = t & 15, ty = t >> 4;
    int n0 = blockIdx.x * 64;
    int m0 = blockIdx.y * 64;

    float acc[4][4];
#pragma unroll
    for (int i = 0; i < 4; ++i)
#pragma unroll
        for (int j = 0; j < 4; ++j) acc[i][j] = 0.f;

    int am  = t >> 2;          // 0..63  (A row within tile)
    int akq = (t & 3) * 4;     // k quad base
    int bk  = t >> 4;          // 0..15  (B k within tile)
    int bn  = (t & 15) * 4;    // n quad base

    const float* Ap = A  + (size_t)(m0 + am) * lda + akq;
    const float* Bp = Bm + (size_t)bk * ldb + n0 + bn;

    for (int k0 = 0; k0 < K; k0 += 16) {
        float4 av = *(const float4*)(Ap + k0);
        float4 bv = *(const float4*)(Bp + (size_t)k0 * ldb);
        __syncthreads();
        As[akq + 0][am] = av.x;
        As[akq + 1][am] = av.y;
        As[akq + 2][am] = av.z;
        As[akq + 3][am] = av.w;
        *(float4*)&Bs[bk][bn] = bv;
        __syncthreads();
#pragma unroll
        for (int k = 0; k < 16; ++k) {
            float4 a4 = *(const float4*)&As[k][ty * 4];
            float4 b4 = *(const float4*)&Bs[k][tx * 4];
            acc[0][0] += a4.x * b4.x; acc[0][1] += a4.x * b4.y;
            acc[0][2] += a4.x * b4.z; acc[0][3] += a4.x * b4.w;
            acc[1][0] += a4.y * b4.x; acc[1][1] += a4.y * b4.y;
            acc[1][2] += a4.y * b4.z; acc[1][3] += a4.y * b4.w;
            acc[2][0] += a4.z * b4.x; acc[2][1] += a4.z * b4.y;
            acc[2][2] += a4.z * b4.z; acc[2][3] += a4.z * b4.w;
            acc[3][0] += a4.w * b4.x; acc[3][1] += a4.w * b4.y;
            acc[3][2] += a4.w * b4.z; acc[3][3] += a4.w * b4.w;
        }
    }
#pragma unroll
    for (int i = 0; i < 4; ++i) {
        int row = m0 + ty * 4 + i;
#pragma unroll
        for (int j = 0; j < 4; ++j) {
            int col = n0 + tx * 4 + j;
            float v = acc[i][j];
            if (bias) v += bias[col];
            C[(size_t)row * ldc + col] = v;
        }
    }
}

// ---------------- area pooling via integral image ------------------------
// grid (192, 4): block = one bh, 16 channels. 256 threads.
__global__ __launch_bounds__(256)
void area_pool_kernel() {
    int bh = blockIdx.x;
    int cbase = blockIdx.y * 16;
    int b = bh / HEADS_, h = bh % HEADS_;
    __shared__ float sat[16][17][17];
    int t = threadIdx.x;

    const int cnts[9] = {256, 240, 224, 240, 225, 210, 224, 210, 196};

    for (int pass = 0; pass < 2; ++pass) {
        int off = (pass == 0) ? DIM_ : 2 * DIM_;   // kh at 768, vh at 1536
        const float* base = g_qkvh + (size_t)(b * N_) * (3 * DIM_) + off + h * DHEAD_ + cbase;

        // phase 1: row-wise prefix sums into sat[c][row+1][x+1]
        {
            int c = t & 15, row = t >> 4;
            if (row == 0)
                for (int x = 0; x < 17; ++x) sat[c][0][x] = 0.f;
            sat[c][row + 1][0] = 0.f;
            float acc = 0.f;
            for (int x = 0; x < 16; ++x) {
                acc += base[(size_t)(row * 16 + x) * (3 * DIM_) + c];
                sat[c][row + 1][x + 1] = acc;
            }
        }
        __syncthreads();
        // phase 2: column-wise prefix down rows
        {
            int c = t & 15, col = (t >> 4) + 1;    // cols 1..16
            float acc = 0.f;
            for (int y = 1; y <= 16; ++y) {
                acc += sat[c][y][col];
                sat[c][y][col] = acc;
            }
        }
        __syncthreads();
        // phase 3: area sums for all 2025 areas
        float* outbuf = (pass == 0) ? g_karea : g_varea;
        for (int m = t; m < MAREA; m += 256) {
            int rem = m, seg = 0;
            while (rem >= cnts[seg]) { rem -= cnts[seg]; ++seg; }
            int ah = seg / 3 + 1, aw = seg % 3 + 1;
            int w = 17 - aw;
            int y0 = rem / w, x0 = rem % w;
            float scale = (pass == 0) ? 1.f / (float)(ah * aw) : 1.f;
            size_t o = ((size_t)bh * MAREA + m) * DHEAD_ + cbase;
#pragma unroll
            for (int c = 0; c < 16; ++c) {
                float s = sat[c][y0 + ah][x0 + aw] - sat[c][y0][x0 + aw]
                        - sat[c][y0 + ah][x0]      + sat[c][y0][x0];
                outbuf[o + c] = s * scale;
            }
        }
        __syncthreads();
    }
}

// ---------------- fused flash-style area attention -----------------------
// grid (192, 2), 128 threads; one thread per query.
__global__ __launch_bounds__(128)
void attn_kernel() {
    int bh = blockIdx.x;
    int n  = blockIdx.y * 128 + threadIdx.x;
    int b = bh / HEADS_, h = bh % HEADS_;

    const float* qp = g_qkvh + (size_t)(b * N_ + n) * (3 * DIM_) + h * DHEAD_;
    float4 q[16];
#pragma unroll
    for (int i = 0; i < 16; ++i) q[i] = *(const float4*)(qp + i * 4);

    __shared__ float4 Ks[32][16];
    __shared__ float4 Vs[32][16];

    float4 o[16];
#pragma unroll
    for (int i = 0; i < 16; ++i) o[i] = make_float4(0.f, 0.f, 0.f, 0.f);
    float mrun = -1e30f, l = 0.f;

    const float* kb = g_karea + (size_t)bh * MAREA * DHEAD_;
    const float* vb = g_varea + (size_t)bh * MAREA * DHEAD_;

    for (int m0 = 0; m0 < MAREA; m0 += 32) {
        int cnt = min(32, MAREA - m0);
        __syncthreads();
        for (int e = threadIdx.x; e < cnt * 16; e += 128) {
            int r = e >> 4, c = e & 15;
            Ks[r][c] = *(const float4*)(kb + (size_t)(m0 + r) * DHEAD_ + c * 4);
            Vs[r][c] = *(const float4*)(vb + (size_t)(m0 + r) * DHEAD_ + c * 4);
        }
        __syncthreads();
        for (int mm = 0; mm < cnt; ++mm) {
            float s = 0.f;
#pragma unroll
            for (int i = 0; i < 16; ++i) {
                float4 kv = Ks[mm][i];
                s += q[i].x * kv.x + q[i].y * kv.y + q[i].z * kv.z + q[i].w * kv.w;
            }
            if (s > mrun) {             // rare: rescale history
                float sc = __expf(mrun - s);
                l *= sc;
#pragma unroll
                for (int i = 0; i < 16; ++i) {
                    o[i].x *= sc; o[i].y *= sc; o[i].z *= sc; o[i].w *= sc;
                }
                mrun = s;
            }
            float p = __expf(s - mrun);
            l += p;
#pragma unroll
            for (int i = 0; i < 16; ++i) {
                float4 vv = Vs[mm][i];
                o[i].x += p * vv.x; o[i].y += p * vv.y;
                o[i].z += p * vv.z; o[i].w += p * vv.w;
            }
        }
    }
    float invl = 1.f / l;
    float* op = g_attn + (size_t)(b * N_ + n) * DIM_ + h * DHEAD_;
#pragma unroll
    for (int i = 0; i < 16; ++i) {
        float4 v = o[i];
        v.x *= invl; v.y *= invl; v.z *= invl; v.w *= invl;
        *(float4*)(op + i * 4) = v;
    }
}

// ---------------- launch ---------------------------------------------------
extern "C" void kernel_launch(void* const* d_in, const int* in_sizes, int n_in,
                              void* d_out, int out_size) {
    const float* x     = (const float*)d_in[0];
    const float* w_qkv = (const float*)d_in[1];
    const float* w_q   = (const float*)d_in[2];
    const float* b_q   = (const float*)d_in[3];
    const float* w_k   = (const float*)d_in[4];
    const float* b_k   = (const float*)d_in[5];
    const float* w_v   = (const float*)d_in[6];
    const float* b_v   = (const float*)d_in[7];
    const float* w_o   = (const float*)d_in[8];
    const float* b_o   = (const float*)d_in[9];
    float* out = (float*)d_out;

    float* weff;   cudaGetSymbolAddress((void**)&weff,   g_weff);
    float* qkvh;   cudaGetSymbolAddress((void**)&qkvh,   g_qkvh);
    float* biasq;  cudaGetSymbolAddress((void**)&biasq,  g_biasqkv);
    float* attn;   cudaGetSymbolAddress((void**)&attn,   g_attn);

    // 1. concat qkv biases
    bias_concat_kernel<<<3, 768>>>(b_q, b_k, b_v);

    // 2. compose W_eff_{q,k,v} = w_qkv[:, seg] @ w_{q,k,v}   (768x768 each)
    {
        dim3 grid(768 / 64, 768 / 64);
        gemm64_kernel<<<grid, 256>>>(w_qkv +    0, 3 * DIM_, w_q, DIM_,
                                     weff +    0, 3 * DIM_, DIM_, nullptr);
        gemm64_kernel<<<grid, 256>>>(w_qkv +  768, 3 * DIM_, w_k, DIM_,
                                     weff +  768, 3 * DIM_, DIM_, nullptr);
        gemm64_kernel<<<grid, 256>>>(w_qkv + 1536, 3 * DIM_, w_v, DIM_,
                                     weff + 1536, 3 * DIM_, DIM_, nullptr);
    }

    // 3. qh|kh|vh = x @ W_eff + bias   ([4096,768] @ [768,2304])
    {
        dim3 grid((3 * DIM_) / 64, ROWS_ / 64);
        gemm64_kernel<<<grid, 256>>>(x, DIM_, weff, 3 * DIM_,
                                     qkvh, 3 * DIM_, DIM_, biasq);
    }

    // 4. area pooling (integral image): k means + v sums
    {
        dim3 grid(BH_, DHEAD_ / 16);
        area_pool_kernel<<<grid, 256>>>();
    }

    // 5. fused attention with online softmax
    {
        dim3 grid(BH_, N_ / 128);
        attn_kernel<<<grid, 128>>>();
    }

    // 6. output projection: out = attn @ w_o + b_o
    {
        dim3 grid(DIM_ / 64, ROWS_ / 64);
        gemm64_kernel<<<grid, 256>>>(attn, DIM_, w_o, DIM_,
                                     out, DIM_, DIM_, b_o);
    }
}